// round 14
// baseline (speedup 1.0000x reference)
#include <cuda_runtime.h>
#include <math.h>

#define BNUM 8
#define NHW  31
#define LNUM 961
#define FIN  784
#define FOUT 196
#define F2   1568

// -------- scratch (static device globals; allocation-free) --------
__device__ float g_x1 [BNUM*16*16384];
__device__ float g_x2 [BNUM*16*16384];
__device__ float g_x3 [BNUM*32*16384];
__device__ float g_p4 [BNUM*LNUM*FIN];
__device__ float g_p6 [BNUM*LNUM*FIN];
__device__ float g_p62[BNUM*LNUM*F2];
__device__ float g_wf [BNUM*LNUM*FOUT];
__device__ float g_xf [BNUM*LNUM*FOUT];
__device__ float g_Ti [(size_t)BNUM*LNUM*LNUM];
__device__ float g_M  [LNUM*LNUM];
__device__ float g_Mb [LNUM];
__device__ float g_y  [BNUM*LNUM*F2];
__device__ float g_fo [BNUM*32*16384];
__device__ float g_o1 [BNUM*16*16384];

// -------- conv3x3 reflect-pad-1, all COUT channels per thread --------
template<int CIN, int COUT>
__global__ void __launch_bounds__(256) conv3x3_reflect(
    const float* __restrict__ in, const float* __restrict__ wt,
    const float* __restrict__ bias, float* __restrict__ out, int leaky)
{
    __shared__ float ws[COUT*CIN*9];
    int b = blockIdx.y;
    for (int i = threadIdx.x; i < COUT*CIN*9; i += 256) ws[i] = wt[i];
    __syncthreads();
    int p = blockIdx.x*256 + threadIdx.x;
    int h = p >> 7, w = p & 127;
    int hm = (h==0)?1:h-1, hp = (h==127)?126:h+1;
    int wm = (w==0)?1:w-1, wp = (w==127)?126:w+1;
    float acc[COUT];
#pragma unroll
    for (int co = 0; co < COUT; co++) acc[co] = bias ? bias[co] : 0.f;
    const float* ib = in + (size_t)b*CIN*16384;
    for (int ci = 0; ci < CIN; ci++) {
        const float* base = ib + ci*16384;
        float v00=base[hm*128+wm], v01=base[hm*128+w], v02=base[hm*128+wp];
        float v10=base[h *128+wm], v11=base[h *128+w], v12=base[h *128+wp];
        float v20=base[hp*128+wm], v21=base[hp*128+w], v22=base[hp*128+wp];
#pragma unroll
        for (int co = 0; co < COUT; co++) {
            const float* wc = ws + co*CIN*9 + ci*9;
            acc[co] += v00*wc[0]+v01*wc[1]+v02*wc[2]
                     + v10*wc[3]+v11*wc[4]+v12*wc[5]
                     + v20*wc[6]+v21*wc[7]+v22*wc[8];
        }
    }
#pragma unroll
    for (int co = 0; co < COUT; co++) {
        float v = acc[co];
        if (leaky) v = (v >= 0.f) ? v : 0.2f*v;
        out[((size_t)b*COUT+co)*16384 + p] = v;
    }
}

// -------- conv1x1 (optional leaky then residual) --------
template<int CIN, int COUT>
__global__ void __launch_bounds__(256) conv1x1_kernel(
    const float* __restrict__ in, const float* __restrict__ wt,
    const float* __restrict__ bias, const float* __restrict__ residual,
    float* __restrict__ out, int leaky)
{
    __shared__ float ws[COUT*CIN];
    int b = blockIdx.y;
    for (int i = threadIdx.x; i < COUT*CIN; i += 256) ws[i] = wt[i];
    __syncthreads();
    int p = blockIdx.x*256 + threadIdx.x;
    const float* ib = in + (size_t)b*CIN*16384 + p;
    float xin[CIN];
#pragma unroll
    for (int ci = 0; ci < CIN; ci++) xin[ci] = ib[ci*16384];
#pragma unroll
    for (int co = 0; co < COUT; co++) {
        float acc = bias ? bias[co] : 0.f;
#pragma unroll
        for (int ci = 0; ci < CIN; ci++) acc += xin[ci]*ws[co*CIN+ci];
        if (leaky) acc = (acc >= 0.f) ? acc : 0.2f*acc;
        if (residual) acc += residual[((size_t)b*COUT+co)*16384 + p];
        out[((size_t)b*COUT+co)*16384 + p] = acc;
    }
}

// -------- unfold: dst[b][l][c*49+kh*7+kw] = src[b,c,ih*4+kh,iw*4+kw] --------
__global__ void unfold_kernel(const float* __restrict__ src,
                              float* __restrict__ dst, int C)
{
    int F = C*49;
    long long total = (long long)BNUM*LNUM*F;
    long long idx = (long long)blockIdx.x*256 + threadIdx.x;
    if (idx >= total) return;
    int f = (int)(idx % F);
    int t = (int)(idx / F);
    int l = t % LNUM, b = t / LNUM;
    int c = f / 49, r = f % 49;
    int kh = r / 7, kw = r % 7;
    int ih = l / NHW, iw = l % NHW;
    dst[idx] = src[(((size_t)b*C + c) << 14) + (ih*4+kh)*128 + (iw*4+kw)];
}

__global__ void addvec(const float* __restrict__ a, const float* __restrict__ b,
                       float* __restrict__ o, int n)
{
    int i = blockIdx.x*256 + threadIdx.x;
    if (i < n) o[i] = a[i] + b[i];
}

// -------- SGEMM 128x128x16, 8x8 micro-tile --------
// C[m][n] = sum_k A[m][k] * (transB ? B[n][k] : B[k][n]) + biasRow[m] + biasCol[n]
__global__ void __launch_bounds__(256,2) sgemm(
    const float* __restrict__ A, long long sA,
    const float* __restrict__ Bm, long long sB,
    float* __restrict__ C, long long sC,
    int M, int N, int K,
    const float* __restrict__ biasRow, const float* __restrict__ biasCol,
    int transB)
{
    __shared__ float As[16][132];
    __shared__ float Bs[16][132];
    A  += (long long)blockIdx.z * sA;
    Bm += (long long)blockIdx.z * sB;
    C  += (long long)blockIdx.z * sC;
    int m0 = blockIdx.y*128, n0 = blockIdx.x*128;
    int tid = threadIdx.x;
    int tx = tid & 15, ty = tid >> 4;
    float acc[8][8];
#pragma unroll
    for (int i = 0; i < 8; i++)
#pragma unroll
        for (int j = 0; j < 8; j++) acc[i][j] = 0.f;

    for (int k0 = 0; k0 < K; k0 += 16) {
#pragma unroll
        for (int it = 0; it < 8; it++) {
            int e = tid + it*256;
            int kk = e & 15, row = e >> 4;
            int gm = m0+row, gk = k0+kk;
            As[kk][row] = (gm < M && gk < K) ? A[(long long)gm*K + gk] : 0.f;
        }
        if (transB) {
#pragma unroll
            for (int it = 0; it < 8; it++) {
                int e = tid + it*256;
                int kk = e & 15, row = e >> 4;
                int gn = n0+row, gk = k0+kk;
                Bs[kk][row] = (gn < N && gk < K) ? Bm[(long long)gn*K + gk] : 0.f;
            }
        } else {
#pragma unroll
            for (int it = 0; it < 8; it++) {
                int e = tid + it*256;
                int nn = e & 127, kk = e >> 7;
                int gn = n0+nn, gk = k0+kk;
                Bs[kk][nn] = (gk < K && gn < N) ? Bm[(long long)gk*N + gn] : 0.f;
            }
        }
        __syncthreads();
#pragma unroll
        for (int kk = 0; kk < 16; kk++) {
            float a[8], bb[8];
#pragma unroll
            for (int i = 0; i < 8; i++) a[i]  = As[kk][ty*8+i];
#pragma unroll
            for (int j = 0; j < 8; j++) bb[j] = Bs[kk][tx*8+j];
#pragma unroll
            for (int i = 0; i < 8; i++)
#pragma unroll
                for (int j = 0; j < 8; j++)
                    acc[i][j] += a[i]*bb[j];
        }
        __syncthreads();
    }
#pragma unroll
    for (int i = 0; i < 8; i++) {
        int gm = m0 + ty*8 + i;
        if (gm >= M) break;
        float br = biasRow ? biasRow[gm] : 0.f;
#pragma unroll
        for (int j = 0; j < 8; j++) {
            int gn = n0 + tx*8 + j;
            if (gn >= N) break;
            C[(long long)gm*N + gn] = acc[i][j] + br + (biasCol ? biasCol[gn] : 0.f);
        }
    }
}

// -------- masked softmax (in place on Am; FTZ-emulated sigmoid mask) --------
// mask = sigmoid(Ti) computed with FTZ: subnormal results (Ti < -87.336)
// flush to exact 0, so mask_b = (mask != 0) zeroes exactly those entries.
// Calibrated against three measured error points (R8/R9/R12).
__global__ void __launch_bounds__(256) softmax_mask_kernel(
    const float* __restrict__ Ti, float* __restrict__ Am)
{
    long long row = blockIdx.x;
    const float* ti = Ti + row*LNUM;
    float* a = Am + row*LNUM;
    const float scale = 1.0f/14.0f;  // 196^-0.5
    float s[4], mb[4], e[4];
    int tid = threadIdx.x;
    float mx = -INFINITY;
#pragma unroll
    for (int q = 0; q < 4; q++) {
        int m = tid + q*256;
        if (m < LNUM) {
            float t = ti[m];
            float mask = 1.f/(1.f + expf(-t));
            if (mask < 1.17549435e-38f) mask = 0.f;   // FTZ: subnormal -> 0
            float sv = a[m]*mask*scale;
            s[q] = sv; mb[q] = (mask != 0.f) ? 1.f : 0.f;
            mx = fmaxf(mx, sv);
        } else { s[q] = -INFINITY; mb[q] = 0.f; }
    }
    __shared__ float red[256];
    red[tid] = mx; __syncthreads();
    for (int st = 128; st > 0; st >>= 1) {
        if (tid < st) red[tid] = fmaxf(red[tid], red[tid+st]);
        __syncthreads();
    }
    mx = red[0]; __syncthreads();
    float sum = 0.f;
#pragma unroll
    for (int q = 0; q < 4; q++) {
        int m = tid + q*256;
        if (m < LNUM) { e[q] = expf(s[q] - mx); sum += e[q]; } else e[q] = 0.f;
    }
    red[tid] = sum; __syncthreads();
    for (int st = 128; st > 0; st >>= 1) {
        if (tid < st) red[tid] += red[tid+st];
        __syncthreads();
    }
    float inv = 1.f/red[0];
#pragma unroll
    for (int q = 0; q < 4; q++) {
        int m = tid + q*256;
        if (m < LNUM) a[m] = e[q]*inv*mb[q];
    }
}

// -------- fold: gather <=4 overlapping patches per output pixel --------
__global__ void fold_kernel(const float* __restrict__ y, float* __restrict__ out)
{
    long long idx = (long long)blockIdx.x*256 + threadIdx.x;
    int p = (int)(idx & 16383);
    int t = (int)(idx >> 14);
    int c = t & 31, b = t >> 5;
    int h = p >> 7, w = p & 127;
    float acc = 0.f;
    int rh = h & 3, rw = w & 3;
    for (int kh = rh; kh < 7; kh += 4) {
        int ihh = h - kh;
        if (ihh < 0) continue;
        int ih = ihh >> 2;
        if (ih > 30) continue;
        for (int kw = rw; kw < 7; kw += 4) {
            int iww = w - kw;
            if (iww < 0) continue;
            int iw = iww >> 2;
            if (iw > 30) continue;
            acc += y[((long long)b*LNUM + ih*NHW + iw)*F2 + c*49 + kh*7 + kw];
        }
    }
    out[idx] = acc;
}

// -------- launcher --------
extern "C" void kernel_launch(void* const* d_in, const int* in_sizes, int n_in,
                              void* d_out, int out_size)
{
    const float* x      = (const float*)d_in[0];
    const float* gw     = (const float*)d_in[1];
    const float* gb     = (const float*)d_in[2];
    const float* ww     = (const float*)d_in[3];
    const float* wb     = (const float*)d_in[4];
    const float* thw    = (const float*)d_in[5];
    const float* thb    = (const float*)d_in[6];
    const float* fc1w   = (const float*)d_in[7];
    const float* fc1b   = (const float*)d_in[8];
    const float* mconvw = (const float*)d_in[9];
    const float* mconvb = (const float*)d_in[10];
    const float* mfcw   = (const float*)d_in[11];
    const float* mfcb   = (const float*)d_in[12];
    const float* c1w    = (const float*)d_in[13];
    const float* c2w    = (const float*)d_in[14];

    float *x1,*x2,*x3,*p4,*p6,*p62,*wf,*xf,*Ti,*Mm,*Mb,*y,*fo,*o1;
    cudaGetSymbolAddress((void**)&x1,  g_x1);
    cudaGetSymbolAddress((void**)&x2,  g_x2);
    cudaGetSymbolAddress((void**)&x3,  g_x3);
    cudaGetSymbolAddress((void**)&p4,  g_p4);
    cudaGetSymbolAddress((void**)&p6,  g_p6);
    cudaGetSymbolAddress((void**)&p62, g_p62);
    cudaGetSymbolAddress((void**)&wf,  g_wf);
    cudaGetSymbolAddress((void**)&xf,  g_xf);
    cudaGetSymbolAddress((void**)&Ti,  g_Ti);
    cudaGetSymbolAddress((void**)&Mm,  g_M);
    cudaGetSymbolAddress((void**)&Mb,  g_Mb);
    cudaGetSymbolAddress((void**)&y,   g_y);
    cudaGetSymbolAddress((void**)&fo,  g_fo);
    cudaGetSymbolAddress((void**)&o1,  g_o1);

    float* Am     = (float*)d_out;                      // (8,961,961)
    float* outimg = Am + (size_t)BNUM*LNUM*LNUM;        // (8,32,128,128)

    dim3 gconv(64, BNUM);
    conv3x3_reflect<32,16><<<gconv,256>>>(x, gw, gb, x1, 0);
    conv3x3_reflect<32,16><<<gconv,256>>>(x, ww, wb, x2, 0);
    conv1x1_kernel<16,32><<<gconv,256>>>(x1, thw, thb, nullptr, x3, 0);

    long long n16 = (long long)BNUM*LNUM*FIN;
    long long n32 = (long long)BNUM*LNUM*F2;
    unfold_kernel<<<(int)((n16+255)/256),256>>>(x1, p6, 16);
    unfold_kernel<<<(int)((n16+255)/256),256>>>(x2, p4, 16);
    unfold_kernel<<<(int)((n32+255)/256),256>>>(x3, p62, 32);

    long long sP = (long long)LNUM*FIN, sF = (long long)LNUM*FOUT;
    long long sL = (long long)LNUM*LNUM, sY = (long long)LNUM*F2;

    // wf = p4 @ fc1^T + fc1_b ; xf = p6 @ fc1^T + fc1_b
    sgemm<<<dim3(2,8,BNUM),256>>>(p4, sP, fc1w, 0, wf, sF, LNUM, FOUT, FIN, nullptr, fc1b, 1);
    sgemm<<<dim3(2,8,BNUM),256>>>(p6, sP, fc1w, 0, xf, sF, LNUM, FOUT, FIN, nullptr, fc1b, 1);

    // A = wf @ xf^T  -> written straight into Am (d_out)
    sgemm<<<dim3(8,8,BNUM),256>>>(wf, sF, xf, sF, Am, sL, LNUM, LNUM, FOUT, nullptr, nullptr, 1);

    // combined mask matrix + bias
    addvec<<<(LNUM*LNUM+255)/256,256>>>(mconvw, mfcw, Mm, LNUM*LNUM);
    addvec<<<(LNUM+255)/256,256>>>(mconvb, mfcb, Mb, LNUM);

    // Ti[b] = Mm @ A[b] + Mb[:,None]
    sgemm<<<dim3(8,8,BNUM),256>>>(Mm, 0, Am, sL, Ti, sL, LNUM, LNUM, LNUM, Mb, nullptr, 0);

    // Am = softmax(A * sigmoid(Ti) * scale) * (sigmoid(Ti) != 0)   (in place)
    softmax_mask_kernel<<<BNUM*LNUM,256>>>(Ti, Am);

    // y = Am @ p62
    sgemm<<<dim3(13,8,BNUM),256>>>(Am, sL, p62, sY, y, sY, LNUM, F2, LNUM, nullptr, nullptr, 0);

    // fold
    fold_kernel<<<(int)(((long long)BNUM*32*16384+255)/256),256>>>(y, fo);

    // o = leaky(conv3x3(refpad(fold), c1_w)); o = leaky(conv1x1(o, c2_w)); out = x + o
    conv3x3_reflect<32,16><<<gconv,256>>>(fo, c1w, nullptr, o1, 1);
    conv1x1_kernel<16,32><<<gconv,256>>>(o1, c2w, nullptr, x, outimg, 1);
}

// round 16
// speedup vs baseline: 1.3055x; 1.3055x over previous
#include <cuda_runtime.h>
#include <math.h>

#define BNUM 8
#define NHW  31
#define LNUM 961
#define FIN  784
#define FOUT 196
#define F2   1568

// padded leading dims
#define LD_A   976     // Am / Mm / Ti K- and N-padding (961 -> 976, /16)
#define LD_WF  208     // FOUT 196 -> 208
#define LD_P62 1664    // F2 1568 -> 1664 (covers 13*128 grid reads)
#define PR_L   1024    // row padding for l-indexed matrices read as A-operand
#define PR_K   976     // row padding for K-indexed B operands

// -------- scratch (static device globals; zero-initialized, allocation-free) --------
__device__ float g_x1 [BNUM*16*16384];
__device__ float g_x2 [BNUM*16*16384];
__device__ float g_x3 [BNUM*32*16384];
__device__ float g_p4 [BNUM*PR_L*FIN];
__device__ float g_p6 [BNUM*PR_L*FIN];
__device__ float g_p62[(size_t)BNUM*PR_K*LD_P62];
__device__ float g_wf [BNUM*PR_L*LD_WF];
__device__ float g_xf [BNUM*PR_L*LD_WF];
__device__ float g_A  [(size_t)BNUM*PR_L*LD_A];
__device__ float g_Ti [(size_t)BNUM*PR_K*LD_A];
__device__ float g_Mp [PR_L*LD_A];
__device__ float g_Mb [LNUM];
__device__ float g_y  [(size_t)BNUM*PR_K*LD_P62];
__device__ float g_fc1[256*FIN];
__device__ float g_fo [BNUM*32*16384];
__device__ float g_o1 [BNUM*16*16384];

// -------- conv3x3 reflect-pad-1, all COUT channels per thread --------
template<int CIN, int COUT>
__global__ void __launch_bounds__(256) conv3x3_reflect(
    const float* __restrict__ in, const float* __restrict__ wt,
    const float* __restrict__ bias, float* __restrict__ out, int leaky)
{
    __shared__ float ws[COUT*CIN*9];
    int b = blockIdx.y;
    for (int i = threadIdx.x; i < COUT*CIN*9; i += 256) ws[i] = wt[i];
    __syncthreads();
    int p = blockIdx.x*256 + threadIdx.x;
    int h = p >> 7, w = p & 127;
    int hm = (h==0)?1:h-1, hp = (h==127)?126:h+1;
    int wm = (w==0)?1:w-1, wp = (w==127)?126:w+1;
    float acc[COUT];
#pragma unroll
    for (int co = 0; co < COUT; co++) acc[co] = bias ? bias[co] : 0.f;
    const float* ib = in + (size_t)b*CIN*16384;
    for (int ci = 0; ci < CIN; ci++) {
        const float* base = ib + ci*16384;
        float v00=base[hm*128+wm], v01=base[hm*128+w], v02=base[hm*128+wp];
        float v10=base[h *128+wm], v11=base[h *128+w], v12=base[h *128+wp];
        float v20=base[hp*128+wm], v21=base[hp*128+w], v22=base[hp*128+wp];
#pragma unroll
        for (int co = 0; co < COUT; co++) {
            const float* wc = ws + co*CIN*9 + ci*9;
            acc[co] += v00*wc[0]+v01*wc[1]+v02*wc[2]
                     + v10*wc[3]+v11*wc[4]+v12*wc[5]
                     + v20*wc[6]+v21*wc[7]+v22*wc[8];
        }
    }
#pragma unroll
    for (int co = 0; co < COUT; co++) {
        float v = acc[co];
        if (leaky) v = (v >= 0.f) ? v : 0.2f*v;
        out[((size_t)b*COUT+co)*16384 + p] = v;
    }
}

// -------- conv1x1 (optional leaky then residual) --------
template<int CIN, int COUT>
__global__ void __launch_bounds__(256) conv1x1_kernel(
    const float* __restrict__ in, const float* __restrict__ wt,
    const float* __restrict__ bias, const float* __restrict__ residual,
    float* __restrict__ out, int leaky)
{
    __shared__ float ws[COUT*CIN];
    int b = blockIdx.y;
    for (int i = threadIdx.x; i < COUT*CIN; i += 256) ws[i] = wt[i];
    __syncthreads();
    int p = blockIdx.x*256 + threadIdx.x;
    const float* ib = in + (size_t)b*CIN*16384 + p;
    float xin[CIN];
#pragma unroll
    for (int ci = 0; ci < CIN; ci++) xin[ci] = ib[ci*16384];
#pragma unroll
    for (int co = 0; co < COUT; co++) {
        float acc = bias ? bias[co] : 0.f;
#pragma unroll
        for (int ci = 0; ci < CIN; ci++) acc += xin[ci]*ws[co*CIN+ci];
        if (leaky) acc = (acc >= 0.f) ? acc : 0.2f*acc;
        if (residual) acc += residual[((size_t)b*COUT+co)*16384 + p];
        out[((size_t)b*COUT+co)*16384 + p] = acc;
    }
}

// -------- unfold into padded layout --------
__global__ void unfold_kernel(const float* __restrict__ src,
                              float* __restrict__ dst, int C, int ld, int pr)
{
    int F = C*49;
    long long total = (long long)BNUM*LNUM*F;
    long long idx = (long long)blockIdx.x*256 + threadIdx.x;
    if (idx >= total) return;
    int f = (int)(idx % F);
    int t = (int)(idx / F);
    int l = t % LNUM, b = t / LNUM;
    int c = f / 49, r = f % 49;
    int kh = r / 7, kw = r % 7;
    int ih = l / NHW, iw = l % NHW;
    dst[((size_t)b*pr + l)*ld + f] =
        src[(((size_t)b*C + c) << 14) + (ih*4+kh)*128 + (iw*4+kw)];
}

__global__ void addvec(const float* __restrict__ a, const float* __restrict__ b,
                       float* __restrict__ o, int n)
{
    int i = blockIdx.x*256 + threadIdx.x;
    if (i < n) o[i] = a[i] + b[i];
}

// Mp[n*LD_A + c] = mconv[n*961+c] + mfc[n*961+c]
__global__ void fill_Mp(const float* __restrict__ a, const float* __restrict__ b,
                        float* __restrict__ o)
{
    int i = blockIdx.x*256 + threadIdx.x;
    if (i >= LNUM*LNUM) return;
    int n = i / LNUM, c = i % LNUM;
    o[n*LD_A + c] = a[i] + b[i];
}

__global__ void copy_fc1(const float* __restrict__ src, float* __restrict__ dst)
{
    int i = blockIdx.x*256 + threadIdx.x;
    if (i < FOUT*FIN) dst[i] = src[i];
}

// -------- double-buffered SGEMM 128x128x16, 8x8 micro-tile, float4 loads ----
// All operand buffers are padded: loads are unconditional; epilogue guarded.
// C[m][n] = sum_k A[m][k] * (transB ? B[n][k] : B[k][n]) + biasRow[m] + biasCol[n]
__global__ void __launch_bounds__(256,2) sgemm(
    const float* __restrict__ Ag, int lda, long long sA,
    const float* __restrict__ Bg, int ldb, long long sB,
    float* __restrict__ Cg, int ldc, long long sC,
    int M, int N, int K,
    const float* __restrict__ biasRow, const float* __restrict__ biasCol,
    int transB)
{
    __shared__ float As[2][16][132];
    __shared__ float Bs[2][16][132];
    const float* A = Ag + (long long)blockIdx.z * sA;
    const float* B = Bg + (long long)blockIdx.z * sB;
    float* C = Cg + (long long)blockIdx.z * sC;
    int m0 = blockIdx.y*128, n0 = blockIdx.x*128;
    int tid = threadIdx.x;
    int tx = tid & 15, ty = tid >> 4;

    int ar = tid >> 2;            // 0..63
    int aq = (tid & 3) * 4;       // 0,4,8,12  (k offset within block)
    int bk = tid >> 5;            // 0..7
    int bn = (tid & 31) * 4;      // 0..124

    const float* Ap0 = A + (long long)(m0 + ar)      * lda + aq;
    const float* Ap1 = A + (long long)(m0 + ar + 64) * lda + aq;
    const float* Bp0, *Bp1;
    if (transB) {
        Bp0 = B + (long long)(n0 + ar)      * ldb + aq;
        Bp1 = B + (long long)(n0 + ar + 64) * ldb + aq;
    } else {
        Bp0 = B + (long long)bk       * ldb + n0 + bn;
        Bp1 = B + (long long)(bk + 8) * ldb + n0 + bn;
    }

    float4 ra0 = *(const float4*)Ap0;
    float4 ra1 = *(const float4*)Ap1;
    float4 rb0 = *(const float4*)Bp0;
    float4 rb1 = *(const float4*)Bp1;

    float acc[8][8];
#pragma unroll
    for (int i = 0; i < 8; i++)
#pragma unroll
        for (int j = 0; j < 8; j++) acc[i][j] = 0.f;

    int NKB = K >> 4;
    for (int kb = 0; kb < NKB; kb++) {
        int buf = kb & 1;
        As[buf][aq+0][ar] = ra0.x; As[buf][aq+1][ar] = ra0.y;
        As[buf][aq+2][ar] = ra0.z; As[buf][aq+3][ar] = ra0.w;
        As[buf][aq+0][ar+64] = ra1.x; As[buf][aq+1][ar+64] = ra1.y;
        As[buf][aq+2][ar+64] = ra1.z; As[buf][aq+3][ar+64] = ra1.w;
        if (transB) {
            Bs[buf][aq+0][ar] = rb0.x; Bs[buf][aq+1][ar] = rb0.y;
            Bs[buf][aq+2][ar] = rb0.z; Bs[buf][aq+3][ar] = rb0.w;
            Bs[buf][aq+0][ar+64] = rb1.x; Bs[buf][aq+1][ar+64] = rb1.y;
            Bs[buf][aq+2][ar+64] = rb1.z; Bs[buf][aq+3][ar+64] = rb1.w;
        } else {
            *(float4*)&Bs[buf][bk  ][bn] = rb0;
            *(float4*)&Bs[buf][bk+8][bn] = rb1;
        }
        __syncthreads();
        if (kb + 1 < NKB) {
            int ko = (kb + 1) << 4;
            ra0 = *(const float4*)(Ap0 + ko);
            ra1 = *(const float4*)(Ap1 + ko);
            if (transB) {
                rb0 = *(const float4*)(Bp0 + ko);
                rb1 = *(const float4*)(Bp1 + ko);
            } else {
                rb0 = *(const float4*)(Bp0 + (long long)ko * ldb);
                rb1 = *(const float4*)(Bp1 + (long long)ko * ldb);
            }
        }
#pragma unroll
        for (int kk = 0; kk < 16; kk++) {
            float4 a0 = *(const float4*)&As[buf][kk][ty*8];
            float4 a1 = *(const float4*)&As[buf][kk][ty*8+4];
            float4 b0 = *(const float4*)&Bs[buf][kk][tx*8];
            float4 b1 = *(const float4*)&Bs[buf][kk][tx*8+4];
            float a[8] = {a0.x,a0.y,a0.z,a0.w,a1.x,a1.y,a1.z,a1.w};
            float b[8] = {b0.x,b0.y,b0.z,b0.w,b1.x,b1.y,b1.z,b1.w};
#pragma unroll
            for (int i = 0; i < 8; i++)
#pragma unroll
                for (int j = 0; j < 8; j++)
                    acc[i][j] += a[i]*b[j];
        }
    }
#pragma unroll
    for (int i = 0; i < 8; i++) {
        int gm = m0 + ty*8 + i;
        if (gm >= M) break;
        float br = biasRow ? biasRow[gm] : 0.f;
#pragma unroll
        for (int j = 0; j < 8; j++) {
            int gn = n0 + tx*8 + j;
            if (gn >= N) break;
            C[(long long)gm*ldc + gn] = acc[i][j] + br + (biasCol ? biasCol[gn] : 0.f);
        }
    }
}

// -------- masked softmax; FTZ-emulated sigmoid mask (calibrated R8/R9/R12/R14) --
// Writes result both into padded g_A (for y-GEMM) and d_out Am.
__global__ void __launch_bounds__(256) softmax_mask_kernel(
    const float* __restrict__ Ti, float* __restrict__ Apad,
    float* __restrict__ AmOut)
{
    int row = blockIdx.x;
    int b = row / LNUM, l = row % LNUM;
    const float* ti = Ti + ((size_t)b*PR_K + l)*LD_A;
    float* a = Apad + ((size_t)b*PR_L + l)*LD_A;
    float* o = AmOut + (size_t)row*LNUM;
    const float scale = 1.0f/14.0f;  // 196^-0.5
    float s[4], mb[4], e[4];
    int tid = threadIdx.x;
    float mx = -INFINITY;
#pragma unroll
    for (int q = 0; q < 4; q++) {
        int m = tid + q*256;
        if (m < LNUM) {
            float t = ti[m];
            float mask = 1.f/(1.f + expf(-t));
            if (mask < 1.17549435e-38f) mask = 0.f;   // FTZ: subnormal -> 0
            float sv = a[m]*mask*scale;
            s[q] = sv; mb[q] = (mask != 0.f) ? 1.f : 0.f;
            mx = fmaxf(mx, sv);
        } else { s[q] = -INFINITY; mb[q] = 0.f; }
    }
    __shared__ float red[256];
    red[tid] = mx; __syncthreads();
    for (int st = 128; st > 0; st >>= 1) {
        if (tid < st) red[tid] = fmaxf(red[tid], red[tid+st]);
        __syncthreads();
    }
    mx = red[0]; __syncthreads();
    float sum = 0.f;
#pragma unroll
    for (int q = 0; q < 4; q++) {
        int m = tid + q*256;
        if (m < LNUM) { e[q] = expf(s[q] - mx); sum += e[q]; } else e[q] = 0.f;
    }
    red[tid] = sum; __syncthreads();
    for (int st = 128; st > 0; st >>= 1) {
        if (tid < st) red[tid] += red[tid+st];
        __syncthreads();
    }
    float inv = 1.f/red[0];
#pragma unroll
    for (int q = 0; q < 4; q++) {
        int m = tid + q*256;
        if (m < LNUM) { float v = e[q]*inv*mb[q]; a[m] = v; o[m] = v; }
    }
}

// -------- fold: gather <=4 overlapping patches per output pixel --------
__global__ void fold_kernel(const float* __restrict__ y, float* __restrict__ out)
{
    long long idx = (long long)blockIdx.x*256 + threadIdx.x;
    int p = (int)(idx & 16383);
    int t = (int)(idx >> 14);
    int c = t & 31, b = t >> 5;
    int h = p >> 7, w = p & 127;
    float acc = 0.f;
    int rh = h & 3, rw = w & 3;
    for (int kh = rh; kh < 7; kh += 4) {
        int ihh = h - kh;
        if (ihh < 0) continue;
        int ih = ihh >> 2;
        if (ih > 30) continue;
        for (int kw = rw; kw < 7; kw += 4) {
            int iww = w - kw;
            if (iww < 0) continue;
            int iw = iww >> 2;
            if (iw > 30) continue;
            acc += y[((size_t)b*PR_K + ih*NHW + iw)*LD_P62 + c*49 + kh*7 + kw];
        }
    }
    out[idx] = acc;
}

// -------- launcher --------
extern "C" void kernel_launch(void* const* d_in, const int* in_sizes, int n_in,
                              void* d_out, int out_size)
{
    const float* x      = (const float*)d_in[0];
    const float* gw     = (const float*)d_in[1];
    const float* gb     = (const float*)d_in[2];
    const float* ww     = (const float*)d_in[3];
    const float* wb     = (const float*)d_in[4];
    const float* thw    = (const float*)d_in[5];
    const float* thb    = (const float*)d_in[6];
    const float* fc1w   = (const float*)d_in[7];
    const float* fc1b   = (const float*)d_in[8];
    const float* mconvw = (const float*)d_in[9];
    const float* mconvb = (const float*)d_in[10];
    const float* mfcw   = (const float*)d_in[11];
    const float* mfcb   = (const float*)d_in[12];
    const float* c1w    = (const float*)d_in[13];
    const float* c2w    = (const float*)d_in[14];

    float *x1,*x2,*x3,*p4,*p6,*p62,*wf,*xf,*Ap,*Ti,*Mp,*Mb,*y,*fo,*o1,*fc1;
    cudaGetSymbolAddress((void**)&x1,  g_x1);
    cudaGetSymbolAddress((void**)&x2,  g_x2);
    cudaGetSymbolAddress((void**)&x3,  g_x3);
    cudaGetSymbolAddress((void**)&p4,  g_p4);
    cudaGetSymbolAddress((void**)&p6,  g_p6);
    cudaGetSymbolAddress((void**)&p62, g_p62);
    cudaGetSymbolAddress((void**)&wf,  g_wf);
    cudaGetSymbolAddress((void**)&xf,  g_xf);
    cudaGetSymbolAddress((void**)&Ap,  g_A);
    cudaGetSymbolAddress((void**)&Ti,  g_Ti);
    cudaGetSymbolAddress((void**)&Mp,  g_Mp);
    cudaGetSymbolAddress((void**)&Mb,  g_Mb);
    cudaGetSymbolAddress((void**)&y,   g_y);
    cudaGetSymbolAddress((void**)&fo,  g_fo);
    cudaGetSymbolAddress((void**)&o1,  g_o1);
    cudaGetSymbolAddress((void**)&fc1, g_fc1);

    float* Am     = (float*)d_out;                      // (8,961,961)
    float* outimg = Am + (size_t)BNUM*LNUM*LNUM;        // (8,32,128,128)

    dim3 gconv(64, BNUM);
    conv3x3_reflect<32,16><<<gconv,256>>>(x, gw, gb, x1, 0);
    conv3x3_reflect<32,16><<<gconv,256>>>(x, ww, wb, x2, 0);
    conv1x1_kernel<16,32><<<gconv,256>>>(x1, thw, thb, nullptr, x3, 0);

    long long n16 = (long long)BNUM*LNUM*FIN;
    long long n32 = (long long)BNUM*LNUM*F2;
    unfold_kernel<<<(int)((n16+255)/256),256>>>(x1, p6, 16, FIN, PR_L);
    unfold_kernel<<<(int)((n16+255)/256),256>>>(x2, p4, 16, FIN, PR_L);
    unfold_kernel<<<(int)((n32+255)/256),256>>>(x3, p62, 32, LD_P62, PR_K);

    copy_fc1<<<(FOUT*FIN+255)/256,256>>>(fc1w, fc1);
    fill_Mp<<<(LNUM*LNUM+255)/256,256>>>(mconvw, mfcw, Mp);
    addvec<<<(LNUM+255)/256,256>>>(mconvb, mfcb, Mb, LNUM);

    // wf = p4 @ fc1^T + fc1_b ; xf = p6 @ fc1^T + fc1_b
    sgemm<<<dim3(2,8,BNUM),256>>>(p4, FIN, (long long)PR_L*FIN,
                                  fc1, FIN, 0,
                                  wf, LD_WF, (long long)PR_L*LD_WF,
                                  LNUM, FOUT, FIN, nullptr, fc1b, 1);
    sgemm<<<dim3(2,8,BNUM),256>>>(p6, FIN, (long long)PR_L*FIN,
                                  fc1, FIN, 0,
                                  xf, LD_WF, (long long)PR_L*LD_WF,
                                  LNUM, FOUT, FIN, nullptr, fc1b, 1);

    // A = wf @ xf^T  -> padded g_A   (K padded 196->208, zero cols)
    sgemm<<<dim3(8,8,BNUM),256>>>(wf, LD_WF, (long long)PR_L*LD_WF,
                                  xf, LD_WF, (long long)PR_L*LD_WF,
                                  Ap, LD_A, (long long)PR_L*LD_A,
                                  LNUM, LNUM, LD_WF, nullptr, nullptr, 1);

    // Ti[b] = (mconv+mfc) @ A[b] + (mconvb+mfcb)[:,None]   (K padded 961->976)
    sgemm<<<dim3(8,8,BNUM),256>>>(Mp, LD_A, 0,
                                  Ap, LD_A, (long long)PR_L*LD_A,
                                  Ti, LD_A, (long long)PR_K*LD_A,
                                  LNUM, LNUM, LD_A, Mb, nullptr, 0);

    // Am = softmax(A * sigmoid_ftz(Ti) * scale) * (mask != 0)
    softmax_mask_kernel<<<BNUM*LNUM,256>>>(Ti, Ap, Am);

    // y = Am @ p62   (K padded 961->976; zero pad rows/cols)
    sgemm<<<dim3(13,8,BNUM),256>>>(Ap, LD_A, (long long)PR_L*LD_A,
                                  p62, LD_P62, (long long)PR_K*LD_P62,
                                  y, LD_P62, (long long)PR_K*LD_P62,
                                  LNUM, F2, LD_A, nullptr, nullptr, 0);

    // fold
    fold_kernel<<<(int)(((long long)BNUM*32*16384+255)/256),256>>>(y, fo);

    // o = leaky(conv3x3(refpad(fold), c1_w)); o = leaky(conv1x1(o, c2_w)); out = x + o
    conv3x3_reflect<32,16><<<gconv,256>>>(fo, c1w, nullptr, o1, 1);
    conv1x1_kernel<16,32><<<gconv,256>>>(o1, c2w, nullptr, x, outimg, 1);
}